// round 6
// baseline (speedup 1.0000x reference)
#include <cuda_runtime.h>
#include <cuda_fp16.h>
#include <cstdint>

#define WSIZE 9216
#define PSTRIDE 9248

#define XPITCH 24                        // words per pixel: 16 data + 8 pad (24 mod 32 = 24 -> LDS.64 conflict-free)
#define XROWW  (130 * XPITCH)            // 3120
#define XT_WORDS (4 * XROWW)             // 12480 (4 input rows per CTA)
#define WPITCH 152                       // words per filter f: 144 data + 8 pad (152 mod 32 = 24)
#define WT_WORDS (32 * WPITCH)           // 4864
#define SMEM_BYTES ((XT_WORDS + WT_WORDS) * 4)   // 69376

// precomputed W^T fp16, paired-k interleaved: [b][f][WPITCH]
__device__ uint32_t gWT[32 * WT_WORDS];

__device__ __forceinline__ uint32_t pack2(float a, float b) {
    __half2 h = __floats2half2_rn(a, b);
    return *(uint32_t*)&h;
}

__device__ __forceinline__ void mma_f16(float& c0, float& c1, float& c2, float& c3,
                                        uint32_t a0, uint32_t a1, uint32_t a2, uint32_t a3,
                                        uint32_t b0, uint32_t b1) {
    asm volatile(
        "mma.sync.aligned.m16n8k16.row.col.f32.f16.f16.f32 "
        "{%0,%1,%2,%3}, {%4,%5,%6,%7}, {%8,%9}, {%0,%1,%2,%3};"
        : "+f"(c0), "+f"(c1), "+f"(c2), "+f"(c3)
        : "r"(a0), "r"(a1), "r"(a2), "r"(a3), "r"(b0), "r"(b1));
}

// ---- precompute: transpose + fp16 + paired-k interleave, once per batch ----
// new word n within an 8-word (16-k) block: n=2t   -> old word t   (k=16kb+2t,2t+1)
//                                           n=2t+1 -> old word t+4 (k=16kb+2t+8,2t+9)
__global__ __launch_bounds__(256)
void wprep(const float* __restrict__ params) {
    __shared__ float s[288 * 33];
    const int b = blockIdx.x;
    const int tid = threadIdx.x;
    const float* pw = params + (long)b * PSTRIDE;
    #pragma unroll
    for (int i = tid; i < 9216; i += 256) {
        int k = i >> 5, f = i & 31;
        s[k * 33 + f] = pw[i];
    }
    __syncthreads();
    uint32_t* gw = gWT + b * WT_WORDS;
    #pragma unroll
    for (int i = tid; i < 32 * 144; i += 256) {
        int f  = i / 144, n = i - f * 144;
        int kb = n >> 3, m = n & 7;
        int o  = (m >> 1) + ((m & 1) << 2);
        int k  = kb * 16 + 2 * o;
        gw[f * WPITCH + n] = pack2(s[k * 33 + f], s[(k + 1) * 33 + f]);
    }
}

__global__ __launch_bounds__(256, 3)
void conv_mma_f16(const float* __restrict__ x, const float* __restrict__ params,
                  float* __restrict__ out) {
    extern __shared__ uint32_t smem[];
    uint32_t* sX = smem;                 // [row 0..3][pix 0..129][XPITCH], paired-k interleaved
    uint32_t* sW = smem + XT_WORDS;      // [f][WPITCH], paired-k interleaved

    const int tid = threadIdx.x;
    const int wid = tid >> 5;
    const int lid = tid & 31;
    const int g   = lid >> 2;
    const int t   = lid & 3;
    const int y0  = blockIdx.x * 2;      // 2 output rows per CTA
    const int b   = blockIdx.y;

    // ---- copy precomputed W^T (pure uint4 memcpy) ----
    const uint4* gw4 = (const uint4*)(gWT + b * WT_WORDS);
    #pragma unroll
    for (int it = 0; it < 5; it++) {
        int idx = tid + it * 256;
        if (idx < WT_WORDS / 4) ((uint4*)sW)[idx] = gw4[idx];
    }

    // ---- build X tile: input rows y0-1 .. y0+2, pixels -1..128 at 0..129, fp16 interleaved ----
    const float* xb = x + (long)b * (128 * 128 * 32);
    #pragma unroll
    for (int it = 0; it < 16; it++) {
        int idx = tid + it * 256;        // 0..4095
        int c4  = idx & 7;
        int px  = (idx >> 3) & 127;
        int row = idx >> 10;             // 0..3
        int gy  = y0 + row - 1;
        float4 s = make_float4(0.f, 0.f, 0.f, 0.f);
        if ((unsigned)gy < 128u)
            s = *(const float4*)(xb + ((gy * 128 + px) * 32 + c4 * 4));
        const int base = row * XROWW + (px + 1) * XPITCH + (c4 >> 2) * 8;
        const int c2 = c4 & 3;
        // old words (2*c2, 2*c2+1) -> new positions per interleave
        const int n1 = (c2 & 1) ? ((c2 >> 1) ? 5 : 4) : ((c2 >> 1) ? 1 : 0);
        const int n2 = n1 + 2;
        sX[base + n1] = pack2(s.x, s.y);
        sX[base + n2] = pack2(s.z, s.w);
    }
    // zero halo pads at pix 0 and 129 (data words 0..15 only)
    if (tid < 128) {
        int row = tid >> 5, rem = tid & 31;
        int pix = (rem >> 4) ? 129 : 0;
        sX[row * XROWW + pix * XPITCH + (rem & 15)] = 0u;
    }
    __syncthreads();

    const int yl = wid >> 2;             // local output row 0..1
    const int m0 = (wid & 3) * 32;       // 32 px per warp

    float acc[2][4][4];
    #pragma unroll
    for (int mi = 0; mi < 2; mi++)
        #pragma unroll
        for (int nt = 0; nt < 4; nt++)
            #pragma unroll
            for (int j = 0; j < 4; j++) acc[mi][nt][j] = 0.f;

    #pragma unroll
    for (int kh = 0; kh < 3; kh++) {
        const uint32_t* xr = sX + (yl + kh) * XROWW;
        #pragma unroll
        for (int kw = 0; kw < 3; kw++) {
            #pragma unroll
            for (int c16 = 0; c16 < 2; c16++) {
                const int kb = kh * 6 + kw * 2 + c16;

                // B fragments: one LDS.64 per n-tile
                uint2 bb[4];
                const uint32_t* wp = sW + kb * 8 + 2 * t;
                #pragma unroll
                for (int nt = 0; nt < 4; nt++)
                    bb[nt] = *(const uint2*)(wp + (nt * 8 + g) * WPITCH);

                #pragma unroll
                for (int mi = 0; mi < 2; mi++) {
                    const uint32_t* ap = xr + (m0 + mi * 16 + g + kw) * XPITCH
                                            + c16 * 8 + 2 * t;
                    uint2 a02 = *(const uint2*)ap;                 // (a0, a2)
                    uint2 a13 = *(const uint2*)(ap + 8 * XPITCH);  // (a1, a3)
                    #pragma unroll
                    for (int nt = 0; nt < 4; nt++)
                        mma_f16(acc[mi][nt][0], acc[mi][nt][1],
                                acc[mi][nt][2], acc[mi][nt][3],
                                a02.x, a13.x, a02.y, a13.y, bb[nt].x, bb[nt].y);
                }
            }
        }
    }

    // ---- epilogue: + bias, store ----
    const float* bp = params + (long)b * PSTRIDE + WSIZE;
    float* ob = out + ((long)(b * 128 + y0 + yl)) * 128 * 32;
    #pragma unroll
    for (int nt = 0; nt < 4; nt++) {
        int f = nt * 8 + t * 2;
        float2 bias = *(const float2*)(bp + f);
        #pragma unroll
        for (int mi = 0; mi < 2; mi++) {
            int px = m0 + mi * 16 + g;
            float2 o0, o1;
            o0.x = acc[mi][nt][0] + bias.x;
            o0.y = acc[mi][nt][1] + bias.y;
            o1.x = acc[mi][nt][2] + bias.x;
            o1.y = acc[mi][nt][3] + bias.y;
            *(float2*)(ob + px * 32 + f)       = o0;
            *(float2*)(ob + (px + 8) * 32 + f) = o1;
        }
    }
}

extern "C" void kernel_launch(void* const* d_in, const int* in_sizes, int n_in,
                              void* d_out, int out_size) {
    const float* x      = (const float*)d_in[0];
    const float* params = (const float*)d_in[1];
    float* out          = (float*)d_out;

    wprep<<<32, 256>>>(params);

    cudaFuncSetAttribute(conv_mma_f16, cudaFuncAttributeMaxDynamicSharedMemorySize, SMEM_BYTES);
    dim3 grid(64, 32);   // (row-pair, batch)
    conv_mma_f16<<<grid, 256, SMEM_BYTES>>>(x, params, out);
}

// round 7
// speedup vs baseline: 1.0597x; 1.0597x over previous
#include <cuda_runtime.h>
#include <cuda_fp16.h>
#include <cstdint>

#define WSIZE 9216
#define PSTRIDE 9248

#define XPITCH 20                        // words/pixel: 16 data + 4 pad; 20*r mod 32 distinct over r=0..7 -> ldmatrix conflict-free
#define XROWW  (130 * XPITCH)            // 2600
#define XT_WORDS (6 * XROWW)             // 15600 (6 input rows)
#define WPITCH 148                       // words/filter: 144 data + 4 pad; 148 mod 32 = 20
#define WT_WORDS (32 * WPITCH)           // 4736
#define SMEM_BYTES ((XT_WORDS + WT_WORDS) * 4)   // 81344

// precomputed W^T fp16, plain k-major: [b][f][WPITCH words], word w = (k=2w, 2w+1)
__device__ uint32_t gWT[32 * WT_WORDS];

__device__ __forceinline__ uint32_t pack2(float a, float b) {
    __half2 h = __floats2half2_rn(a, b);
    return *(uint32_t*)&h;
}
__device__ __forceinline__ uint32_t smem_u32(const void* p) {
    uint32_t a;
    asm("{ .reg .u64 t; cvta.to.shared.u64 t, %1; cvt.u32.u64 %0, t; }" : "=r"(a) : "l"(p));
    return a;
}
__device__ __forceinline__ void ldsm4(uint32_t& r0, uint32_t& r1, uint32_t& r2, uint32_t& r3,
                                      uint32_t addr) {
    asm volatile("ldmatrix.sync.aligned.m8n8.x4.shared.b16 {%0,%1,%2,%3}, [%4];"
                 : "=r"(r0), "=r"(r1), "=r"(r2), "=r"(r3) : "r"(addr));
}
__device__ __forceinline__ void mma_f16(float& c0, float& c1, float& c2, float& c3,
                                        uint32_t a0, uint32_t a1, uint32_t a2, uint32_t a3,
                                        uint32_t b0, uint32_t b1) {
    asm volatile(
        "mma.sync.aligned.m16n8k16.row.col.f32.f16.f16.f32 "
        "{%0,%1,%2,%3}, {%4,%5,%6,%7}, {%8,%9}, {%0,%1,%2,%3};"
        : "+f"(c0), "+f"(c1), "+f"(c2), "+f"(c3)
        : "r"(a0), "r"(a1), "r"(a2), "r"(a3), "r"(b0), "r"(b1));
}

// ---- precompute W^T fp16 (plain k-major), 3 blocks per batch (k split 96) ----
__global__ __launch_bounds__(256)
void wprep(const float* __restrict__ params) {
    __shared__ float s[96 * 33];
    const int b  = blockIdx.x / 3;
    const int kc = blockIdx.x % 3;       // k chunk [kc*96, kc*96+96)
    const int tid = threadIdx.x;
    const float* pw = params + (long)b * PSTRIDE + kc * 96 * 32;
    #pragma unroll
    for (int i = tid; i < 96 * 32; i += 256) {
        int k = i >> 5, f = i & 31;
        s[k * 33 + f] = pw[i];
    }
    __syncthreads();
    uint32_t* gw = gWT + b * WT_WORDS + kc * 48;
    #pragma unroll
    for (int i = tid; i < 32 * 48; i += 256) {
        int f = i / 48, n = i - f * 48;
        gw[f * WPITCH + n] = pack2(s[(2 * n) * 33 + f], s[(2 * n + 1) * 33 + f]);
    }
}

__global__ __launch_bounds__(256, 2)
void conv_mma_f16(const float* __restrict__ x, const float* __restrict__ params,
                  float* __restrict__ out) {
    extern __shared__ uint32_t smem[];
    uint32_t* sX = smem;                 // [row 0..5][pix 0..129][XPITCH], plain k-major fp16
    uint32_t* sW = smem + XT_WORDS;      // [f][WPITCH], plain k-major fp16

    const int tid = threadIdx.x;
    const int wid = tid >> 5;
    const int lid = tid & 31;
    const int y0  = blockIdx.x * 4;      // 4 output rows per CTA
    const int b   = blockIdx.y;

    // ---- copy precomputed W^T (uint4 memcpy) ----
    const uint4* gw4 = (const uint4*)(gWT + b * WT_WORDS);
    #pragma unroll
    for (int it = 0; it < 5; it++) {
        int idx = tid + it * 256;
        if (idx < WT_WORDS / 4) ((uint4*)sW)[idx] = gw4[idx];
    }

    // ---- build X tile: input rows y0-1 .. y0+4, pixels -1..128 at 0..129 ----
    const float* xb = x + (long)b * (128 * 128 * 32);
    #pragma unroll
    for (int it = 0; it < 24; it++) {
        int idx = tid + it * 256;        // 0..6143
        int c4  = idx & 7;               // ci/4
        int px  = (idx >> 3) & 127;
        int row = idx >> 10;             // 0..5
        int gy  = y0 + row - 1;
        uint2 v = make_uint2(0u, 0u);
        if ((unsigned)gy < 128u) {
            float4 s = *(const float4*)(xb + ((gy * 128 + px) * 32 + c4 * 4));
            v.x = pack2(s.x, s.y);
            v.y = pack2(s.z, s.w);
        }
        *(uint2*)(sX + row * XROWW + (px + 1) * XPITCH + c4 * 2) = v;
    }
    if (tid < 192) {
        int row = tid >> 5, rem = tid & 31;
        int pix = (rem >> 4) ? 129 : 0;
        sX[row * XROWW + pix * XPITCH + (rem & 15)] = 0u;
    }
    __syncthreads();

    const int yl = wid >> 1;             // local output row 0..3
    const int m0 = (wid & 1) * 64;       // 64 px per warp

    // ---- lane-fixed ldmatrix base addresses ----
    const uint32_t sx0 = smem_u32(sX);
    const uint32_t sw0 = smem_u32(sW);
    const int pxl = (lid & 7) + ((lid >> 3) & 1) * 8;        // row within m16 tile
    const int kq  = (lid >> 4) * 4;                          // +8 fp16 for a2/a3 lanes
    const uint32_t aBase = sx0 + (uint32_t)(((m0 + pxl) * XPITCH + kq) * 4);
    const int fl   = (lid & 7) + ((lid >> 4) & 1) * 8;       // f row (matrices: nt-lo/hi)
    const int bchk = ((lid >> 3) & 1) * 4;                   // b0 vs b1 chunk
    const uint32_t bBase = sw0 + (uint32_t)((fl * WPITCH + bchk) * 4);

    float acc[4][4][4];
    #pragma unroll
    for (int mi = 0; mi < 4; mi++)
        #pragma unroll
        for (int nt = 0; nt < 4; nt++)
            #pragma unroll
            for (int j = 0; j < 4; j++) acc[mi][nt][j] = 0.f;

    #pragma unroll
    for (int kh = 0; kh < 3; kh++) {
        const uint32_t aRow = aBase + (uint32_t)((yl + kh) * XROWW * 4);
        #pragma unroll
        for (int kw = 0; kw < 3; kw++) {
            #pragma unroll
            for (int c16 = 0; c16 < 2; c16++) {
                const int k0w = kh * 48 + kw * 16 + c16 * 8;   // word offset along k

                // B: two x4 ldmatrix -> all 4 n-tiles
                uint32_t b00, b01, b10, b11, b20, b21, b30, b31;
                ldsm4(b00, b01, b10, b11, bBase + (uint32_t)(k0w * 4));
                ldsm4(b20, b21, b30, b31, bBase + (uint32_t)((k0w + 16 * WPITCH) * 4));

                #pragma unroll
                for (int mi = 0; mi < 4; mi++) {
                    uint32_t a0, a1, a2, a3;
                    ldsm4(a0, a1, a2, a3,
                          aRow + (uint32_t)(((mi * 16 + kw) * XPITCH + c16 * 8) * 4));
                    mma_f16(acc[mi][0][0], acc[mi][0][1], acc[mi][0][2], acc[mi][0][3],
                            a0, a1, a2, a3, b00, b01);
                    mma_f16(acc[mi][1][0], acc[mi][1][1], acc[mi][1][2], acc[mi][1][3],
                            a0, a1, a2, a3, b10, b11);
                    mma_f16(acc[mi][2][0], acc[mi][2][1], acc[mi][2][2], acc[mi][2][3],
                            a0, a1, a2, a3, b20, b21);
                    mma_f16(acc[mi][3][0], acc[mi][3][1], acc[mi][3][2], acc[mi][3][3],
                            a0, a1, a2, a3, b30, b31);
                }
            }
        }
    }

    // ---- epilogue: + bias, store ----
    const int g = lid >> 2, t = lid & 3;
    const float* bp = params + (long)b * PSTRIDE + WSIZE;
    float* ob = out + ((long)(b * 128 + y0 + yl)) * 128 * 32;
    #pragma unroll
    for (int nt = 0; nt < 4; nt++) {
        int f = nt * 8 + t * 2;
        float2 bias = *(const float2*)(bp + f);
        #pragma unroll
        for (int mi = 0; mi < 4; mi++) {
            int px = m0 + mi * 16 + g;
            float2 o0, o1;
            o0.x = acc[mi][nt][0] + bias.x;
            o0.y = acc[mi][nt][1] + bias.y;
            o1.x = acc[mi][nt][2] + bias.x;
            o1.y = acc[mi][nt][3] + bias.y;
            *(float2*)(ob + px * 32 + f)       = o0;
            *(float2*)(ob + (px + 8) * 32 + f) = o1;
        }
    }
}

extern "C" void kernel_launch(void* const* d_in, const int* in_sizes, int n_in,
                              void* d_out, int out_size) {
    const float* x      = (const float*)d_in[0];
    const float* params = (const float*)d_in[1];
    float* out          = (float*)d_out;

    wprep<<<96, 256>>>(params);

    cudaFuncSetAttribute(conv_mma_f16, cudaFuncAttributeMaxDynamicSharedMemorySize, SMEM_BYTES);
    dim3 grid(32, 32);   // (row-quad, batch)
    conv_mma_f16<<<grid, 256, SMEM_BYTES>>>(x, params, out);
}